// round 14
// baseline (speedup 1.0000x reference)
#include <cuda_runtime.h>
#include <cuda_fp16.h>
#include <stdint.h>

// Problem constants
#define BATCH   4
#define HEADS   16
#define SEQ     2048
#define DK      64
#define DMODEL  1024
#define NTOK    (BATCH * SEQ)            // 8192
#define BH      (BATCH * HEADS)          // 64

// Scratch (device globals: cudaMalloc is forbidden)
__device__ __half g_x  [NTOK * DMODEL];          // x fp16
__device__ __half g_wq [3 * DMODEL * DMODEL];
__device__ __half g_wo [DMODEL * DMODEL];
__device__ __half g_q  [BH * SEQ * DK];          // Q fp16 (pre-scaled 1/8)
__device__ __half g_ks [BH * SEQ * DK];          // K fp16
__device__ __half g_vs [BH * SEQ * DK];          // V fp16
__device__ __half g_hs [NTOK * DMODEL];          // heads fp16

// ---------------------------------------------------------------------------
// Warp MMA + async-copy helpers (sm_80+ instructions only)
// ---------------------------------------------------------------------------
__device__ __forceinline__ uint32_t smem_u32(const void* p) {
    uint32_t a;
    asm("{ .reg .u64 t; cvta.to.shared.u64 t, %1; cvt.u32.u64 %0, t; }"
        : "=r"(a) : "l"(p));
    return a;
}
__device__ __forceinline__ void ldsm_x4(uint32_t& r0, uint32_t& r1,
                                        uint32_t& r2, uint32_t& r3, uint32_t addr) {
    asm volatile("ldmatrix.sync.aligned.m8n8.x4.shared.b16 {%0,%1,%2,%3}, [%4];"
                 : "=r"(r0), "=r"(r1), "=r"(r2), "=r"(r3) : "r"(addr));
}
__device__ __forceinline__ void ldsm_x4t(uint32_t& r0, uint32_t& r1,
                                         uint32_t& r2, uint32_t& r3, uint32_t addr) {
    asm volatile("ldmatrix.sync.aligned.m8n8.x4.trans.shared.b16 {%0,%1,%2,%3}, [%4];"
                 : "=r"(r0), "=r"(r1), "=r"(r2), "=r"(r3) : "r"(addr));
}
__device__ __forceinline__ void mma_f16(float* c, const uint32_t* a, const uint32_t* b) {
    asm volatile("mma.sync.aligned.m16n8k16.row.col.f32.f16.f16.f32 "
                 "{%0,%1,%2,%3}, {%4,%5,%6,%7}, {%8,%9}, {%0,%1,%2,%3};"
                 : "+f"(c[0]), "+f"(c[1]), "+f"(c[2]), "+f"(c[3])
                 : "r"(a[0]), "r"(a[1]), "r"(a[2]), "r"(a[3]),
                   "r"(b[0]), "r"(b[1]));
}
__device__ __forceinline__ uint32_t pack_f16(float a, float b) {
    __half2 h = __floats2half2_rn(a, b);
    return *(uint32_t*)&h;
}
__device__ __forceinline__ void cp16(uint32_t s, const void* g) {
    asm volatile("cp.async.cg.shared.global [%0], [%1], 16;" :: "r"(s), "l"(g));
}
#define CP_COMMIT() asm volatile("cp.async.commit_group;")
#define CP_WAIT1()  asm volatile("cp.async.wait_group 1;")

// ---------------------------------------------------------------------------
// Single fused fp32 -> fp16 convert for x, W_qkv, W_o  (one launch)
// ---------------------------------------------------------------------------
#define XN4   (NTOK * DMODEL / 4)                // 2097152
#define WQN4  (3 * DMODEL * DMODEL / 4)          // 786432
#define WON4  (DMODEL * DMODEL / 4)              // 262144
#define CVTN4 (XN4 + WQN4 + WON4)                // 3145728

__global__ __launch_bounds__(256)
void convert_all_kernel(const float4* __restrict__ x,
                        const float4* __restrict__ wq,
                        const float4* __restrict__ wo)
{
    int i = blockIdx.x * blockDim.x + threadIdx.x;
    if (i >= CVTN4) return;
    const float4* src;
    __half* dst;
    int j = i;
    if (j < XN4)            { src = x;  dst = g_x;  }
    else if ((j -= XN4) < WQN4) { src = wq; dst = g_wq; }
    else                    { j -= WQN4; src = wo; dst = g_wo; }
    float4 v = src[j];
    *(__half2*)(dst + 4 * (size_t)j)     = __floats2half2_rn(v.x, v.y);
    *(__half2*)(dst + 4 * (size_t)j + 2) = __floats2half2_rn(v.z, v.w);
}

// ---------------------------------------------------------------------------
// fp16 GEMM on HMMA (R11 config, interleaved B-ldsm/MMA schedule):
// C[M,N] = A[M,K] * B[N,K]^T, K = 1024.
// 256 threads = 8 warps (2m x 4n), warp tile 64x32, BK=64.
// 3-stage cp.async ring, one barrier per k-chunk (16 chunks).
// mode 0: fp32 store to C.  mode 1: QKV epilogue -> per-head fp16 planes.
// ---------------------------------------------------------------------------
#define BKS      64
#define NKI      (DMODEL / BKS)         // 16
#define GROW     144                    // 128B data + 16B pad per row
#define APLANE   (128 * GROW)           // 18432 bytes
#define STAGE_B2 (2 * APLANE)           // A, B
#define NSTG     3
#define GSMEM    (NSTG * STAGE_B2)      // 110592 bytes

__global__ __launch_bounds__(256, 1)
void gemm_f16_kernel(const __half* __restrict__ A,
                     const __half* __restrict__ B,
                     float* __restrict__ C, int N, int mode)
{
    extern __shared__ char smem[];
    const uint32_t sbase = smem_u32(smem);
    const int tid  = threadIdx.x;
    const int wid  = tid >> 5;
    const int lane = tid & 31;
    const int wm   = wid >> 2;          // 0..1  (64-row slab)
    const int wn   = wid & 3;           // 0..3  (32-col slab)
    const int m0   = blockIdx.y * 128;
    const int n0   = blockIdx.x * 128;
    const int K    = DMODEL;

    const __half* gA = A + (size_t)m0 * K;
    const __half* gB = B + (size_t)n0 * K;

    const int r2 = tid >> 1;            // 0..127
    const int c4 = (tid & 1) * 4;       // 16B-chunk base (0 or 4)
    auto issue_stage = [&](int buf, int kc) {
        const uint32_t dst = sbase + buf * STAGE_B2 + r2 * GROW;
        const size_t goff = (size_t)r2 * K + kc;
#pragma unroll
        for (int j = 0; j < 4; ++j) {
            cp16(dst + (c4 + j) * 16,          gA + goff + (c4 + j) * 8);
            cp16(dst + APLANE + (c4 + j) * 16, gB + goff + (c4 + j) * 8);
        }
    };

    issue_stage(0, 0);      CP_COMMIT();
    issue_stage(1, BKS);    CP_COMMIT();

    float acc[4][4][4];
#pragma unroll
    for (int mi = 0; mi < 4; ++mi)
#pragma unroll
        for (int nj = 0; nj < 4; ++nj)
#pragma unroll
            for (int q = 0; q < 4; ++q) acc[mi][nj][q] = 0.0f;

    for (int kt = 0; kt < NKI; ++kt) {
        CP_WAIT1();
        __syncthreads();
        if (kt + 2 < NKI) {
            issue_stage((kt + 2) % NSTG, (kt + 2) * BKS);
            CP_COMMIT();
        }

        const uint32_t sb = sbase + (kt % NSTG) * STAGE_B2;
#pragma unroll
        for (int ks = 0; ks < 4; ++ks) {
            uint32_t a_[4][4];
#pragma unroll
            for (int mi = 0; mi < 4; ++mi) {
                const int row = wm * 64 + mi * 16 + (lane & 15);
                const uint32_t a = sb + row * GROW + ks * 32 + (lane >> 4) * 16;
                ldsm_x4(a_[mi][0], a_[mi][1], a_[mi][2], a_[mi][3], a);
            }
            // interleave: B-pair ldsm then its 8 MMAs, so the next pair's
            // ldsm issues under the current MMA burst
#pragma unroll
            for (int p2 = 0; p2 < 2; ++p2) {
                const int row = wn * 32 + p2 * 16 + (lane & 15);
                const uint32_t a = sb + APLANE + row * GROW
                                 + ks * 32 + (lane >> 4) * 16;
                uint32_t r0, r1, r2x, r3;
                ldsm_x4(r0, r1, r2x, r3, a);
                uint32_t b0[2] = {r0, r2x};
                uint32_t b1[2] = {r1, r3};
#pragma unroll
                for (int mi = 0; mi < 4; ++mi) {
                    mma_f16(acc[mi][2 * p2],     a_[mi], b0);
                    mma_f16(acc[mi][2 * p2 + 1], a_[mi], b1);
                }
            }
        }
    }

#pragma unroll
    for (int mi = 0; mi < 4; ++mi)
#pragma unroll
        for (int nj = 0; nj < 4; ++nj) {
            const int mrow = m0 + wm * 64 + mi * 16 + (lane >> 2);
            const int ncol = n0 + wn * 32 + nj * 8 + (lane & 3) * 2;
            if (mode == 0) {
                *(float2*)(C + (size_t)mrow * N + ncol) =
                    make_float2(acc[mi][nj][0], acc[mi][nj][1]);
                *(float2*)(C + (size_t)(mrow + 8) * N + ncol) =
                    make_float2(acc[mi][nj][2], acc[mi][nj][3]);
            } else {
                const int cc = ncol >> 10;
                const int h  = (ncol >> 6) & (HEADS - 1);
                const int dk = ncol & (DK - 1);
                const float scl = (cc == 0) ? 0.125f : 1.0f;
                __half* dstp = (cc == 0) ? g_q : ((cc == 1) ? g_ks : g_vs);
#pragma unroll
                for (int half_ = 0; half_ < 2; ++half_) {
                    const int m = mrow + half_ * 8;
                    const int b_ = m >> 11;
                    const int s  = m & (SEQ - 1);
                    const size_t off =
                        ((size_t)(b_ * HEADS + h) * SEQ + s) * DK + dk;
                    *(__half2*)(dstp + off) = __floats2half2_rn(
                        acc[mi][nj][half_ * 2] * scl,
                        acc[mi][nj][half_ * 2 + 1] * scl);
                }
            }
        }
}

// ---------------------------------------------------------------------------
// Causal flash attention on HMMA, fp16 (R11 version — register prefetch).
// Grid: (SEQ/128, BH). Block: 256 threads = 8 warps; warp owns 16 q-rows.
// ---------------------------------------------------------------------------
#define ASTR   144                    // 64 fp16 = 128B data + 16 pad
#define A_Q    0
#define A_K    (128 * ASTR)
#define A_V    (A_K + 64 * ASTR)
#define A_TOTAL (A_V + 64 * ASTR)     // 36864 bytes

__global__ __launch_bounds__(256, 1)
void attn_f16_kernel()
{
    extern __shared__ char smem[];
    const uint32_t sb = smem_u32(smem);
    const int tid  = threadIdx.x;
    const int w    = tid >> 5;
    const int lane = tid & 31;
    const int qt   = blockIdx.x;          // 128-row q tile
    const int bh   = blockIdx.y;
    const int q0   = qt * 128;

    const __half* Qs = g_q  + ((size_t)bh * SEQ + q0) * DK;
    const __half* Ks = g_ks + (size_t)bh * SEQ * DK;
    const __half* Vs = g_vs + (size_t)bh * SEQ * DK;

    const int r_ = tid >> 3;              // 0..31
    const int c_ = tid & 7;               // 16B chunk

    // Load Q tile (128 x 64) + KV tile 0 into smem
#pragma unroll
    for (int t = 0; t < 4; ++t) {
        const int row = r_ + t * 32;
        *(uint4*)(smem + A_Q + row * ASTR + c_ * 16) =
            *(const uint4*)(Qs + (size_t)row * DK + c_ * 8);
    }
#pragma unroll
    for (int t = 0; t < 2; ++t) {
        const int row = r_ + t * 32;
        const size_t g = (size_t)row * DK + c_ * 8;
        const int so = row * ASTR + c_ * 16;
        *(uint4*)(smem + A_K + so) = *(const uint4*)(Ks + g);
        *(uint4*)(smem + A_V + so) = *(const uint4*)(Vs + g);
    }
    __syncthreads();

    // Q fragments (registers, whole kernel)
    uint32_t qf[4][4];
#pragma unroll
    for (int kk = 0; kk < 4; ++kk) {
        const int row = w * 16 + (lane & 15);
        const uint32_t a = sb + A_Q + row * ASTR + kk * 32 + (lane >> 4) * 16;
        ldsm_x4(qf[kk][0], qf[kk][1], qf[kk][2], qf[kk][3], a);
    }

    float o[8][4];
#pragma unroll
    for (int nj = 0; nj < 8; ++nj)
#pragma unroll
        for (int q = 0; q < 4; ++q) o[nj][q] = 0.0f;
    float mA = -1e30f, mB = -1e30f, lA = 0.0f, lB = 0.0f;

    const int nkt = 2 * qt + 2;
    for (int kt = 0; kt < nkt; ++kt) {
        // Prefetch next KV tile into registers
        uint4 pf[4];
        const bool havepf = (kt + 1 < nkt);
        if (havepf) {
#pragma unroll
            for (int t = 0; t < 2; ++t) {
                const int row = r_ + t * 32;
                const size_t g = (size_t)((kt + 1) * 64 + row) * DK + c_ * 8;
                pf[t * 2 + 0] = *(const uint4*)(Ks + g);
                pf[t * 2 + 1] = *(const uint4*)(Vs + g);
            }
        }

        // Warps 0-3 fully masked on the last diagonal tile
        if (!(kt == 2 * qt + 1 && w < 4)) {
            // ---- S = Q K^T ----
            float s[8][4];
#pragma unroll
            for (int nj = 0; nj < 8; ++nj)
#pragma unroll
                for (int q = 0; q < 4; ++q) s[nj][q] = 0.0f;

#pragma unroll
            for (int kk = 0; kk < 4; ++kk) {
                uint32_t bk[8][2];
#pragma unroll
                for (int p2 = 0; p2 < 4; ++p2) {
                    const uint32_t a = sb + A_K + (p2 * 16 + (lane & 15)) * ASTR
                                     + kk * 32 + (lane >> 4) * 16;
                    uint32_t r0, r1, r2, r3;
                    ldsm_x4(r0, r1, r2, r3, a);
                    bk[2 * p2][0] = r0; bk[2 * p2][1] = r2;
                    bk[2 * p2 + 1][0] = r1; bk[2 * p2 + 1][1] = r3;
                }
#pragma unroll
                for (int nj = 0; nj < 8; ++nj)
                    mma_f16(s[nj], qf[kk], bk[nj]);
            }

            // ---- causal mask (diagonal tiles only) ----
            if (kt >= 2 * qt) {
                const int rowA = q0 + w * 16 + (lane >> 2);
                const int k0   = kt * 64;
#pragma unroll
                for (int nj = 0; nj < 8; ++nj) {
                    const int c0 = k0 + nj * 8 + (lane & 3) * 2;
                    if (c0 > rowA)     s[nj][0] = -1e30f;
                    if (c0 + 1 > rowA) s[nj][1] = -1e30f;
                    if (c0 > rowA + 8)     s[nj][2] = -1e30f;
                    if (c0 + 1 > rowA + 8) s[nj][3] = -1e30f;
                }
            }

            // ---- online softmax ----
            float tmA = -1e30f, tmB = -1e30f;
#pragma unroll
            for (int nj = 0; nj < 8; ++nj) {
                tmA = fmaxf(tmA, fmaxf(s[nj][0], s[nj][1]));
                tmB = fmaxf(tmB, fmaxf(s[nj][2], s[nj][3]));
            }
            tmA = fmaxf(tmA, __shfl_xor_sync(0xffffffffu, tmA, 1));
            tmA = fmaxf(tmA, __shfl_xor_sync(0xffffffffu, tmA, 2));
            tmB = fmaxf(tmB, __shfl_xor_sync(0xffffffffu, tmB, 1));
            tmB = fmaxf(tmB, __shfl_xor_sync(0xffffffffu, tmB, 2));
            const float mnA = fmaxf(mA, tmA);
            const float mnB = fmaxf(mB, tmB);
            const float fA = __expf(mA - mnA);
            const float fB = __expf(mB - mnB);
            mA = mnA; mB = mnB;

            float rsA = 0.0f, rsB = 0.0f;
#pragma unroll
            for (int nj = 0; nj < 8; ++nj) {
                s[nj][0] = __expf(s[nj][0] - mnA);
                s[nj][1] = __expf(s[nj][1] - mnA);
                s[nj][2] = __expf(s[nj][2] - mnB);
                s[nj][3] = __expf(s[nj][3] - mnB);
                rsA += s[nj][0] + s[nj][1];
                rsB += s[nj][2] + s[nj][3];
            }
            rsA += __shfl_xor_sync(0xffffffffu, rsA, 1);
            rsA += __shfl_xor_sync(0xffffffffu, rsA, 2);
            rsB += __shfl_xor_sync(0xffffffffu, rsB, 1);
            rsB += __shfl_xor_sync(0xffffffffu, rsB, 2);
            lA = lA * fA + rsA;
            lB = lB * fB + rsB;
#pragma unroll
            for (int nj = 0; nj < 8; ++nj) {
                o[nj][0] *= fA; o[nj][1] *= fA;
                o[nj][2] *= fB; o[nj][3] *= fB;
            }

            // ---- O += P V (P rounded to fp16) ----
#pragma unroll
            for (int kk = 0; kk < 4; ++kk) {
                const int j0 = 2 * kk, j1 = 2 * kk + 1;
                uint32_t ph[4];
                ph[0] = pack_f16(s[j0][0], s[j0][1]);
                ph[1] = pack_f16(s[j0][2], s[j0][3]);
                ph[2] = pack_f16(s[j1][0], s[j1][1]);
                ph[3] = pack_f16(s[j1][2], s[j1][3]);
#pragma unroll
                for (int p2 = 0; p2 < 4; ++p2) {
                    const uint32_t a = sb + A_V
                        + (kk * 16 + (lane & 7) + ((lane >> 3) & 1) * 8) * ASTR
                        + p2 * 32 + (lane >> 4) * 16;
                    uint32_t r0, r1, r2, r3;
                    ldsm_x4t(r0, r1, r2, r3, a);
                    uint32_t bv0[2] = {r0, r1}, bv1[2] = {r2, r3};
                    mma_f16(o[2 * p2],     ph, bv0);
                    mma_f16(o[2 * p2 + 1], ph, bv1);
                }
            }
        }

        if (havepf) {
            __syncthreads();
#pragma unroll
            for (int t = 0; t < 2; ++t) {
                const int row = r_ + t * 32;
                const int so = row * ASTR + c_ * 16;
                *(uint4*)(smem + A_K + so) = pf[t * 2 + 0];
                *(uint4*)(smem + A_V + so) = pf[t * 2 + 1];
            }
            __syncthreads();
        }
    }

    // ---- normalize + store heads [b*S+s][h*DK+dk] as fp16 ----
    const int b = bh >> 4;
    const int h = bh & 15;
    const float iA = 1.0f / lA;
    const float iB = 1.0f / lB;
    const int rowA = q0 + w * 16 + (lane >> 2);
#pragma unroll
    for (int nj = 0; nj < 8; ++nj) {
        const int col = h * DK + nj * 8 + (lane & 3) * 2;
        size_t off = (size_t)(b * SEQ + rowA) * DMODEL + col;
        *(__half2*)(g_hs + off) =
            __floats2half2_rn(o[nj][0] * iA, o[nj][1] * iA);
        *(__half2*)(g_hs + off + 8 * DMODEL) =
            __floats2half2_rn(o[nj][2] * iB, o[nj][3] * iB);
    }
}

// ---------------------------------------------------------------------------
extern "C" void kernel_launch(void* const* d_in, const int* in_sizes, int n_in,
                              void* d_out, int out_size)
{
    const float* x     = (const float*)d_in[0];
    const float* w_qkv = (const float*)d_in[1];
    const float* w_o   = (const float*)d_in[2];
    float* out = (float*)d_out;

    __half *xp, *wq, *wo, *hs;
    cudaGetSymbolAddress((void**)&xp, g_x);
    cudaGetSymbolAddress((void**)&wq, g_wq);
    cudaGetSymbolAddress((void**)&wo, g_wo);
    cudaGetSymbolAddress((void**)&hs, g_hs);

    cudaFuncSetAttribute(gemm_f16_kernel,
                         cudaFuncAttributeMaxDynamicSharedMemorySize, GSMEM);
    cudaFuncSetAttribute(attn_f16_kernel,
                         cudaFuncAttributeMaxDynamicSharedMemorySize, A_TOTAL);

    // 1) convert all inputs to fp16 (one launch)
    convert_all_kernel<<<(CVTN4 + 255) / 256, 256>>>(
        (const float4*)x, (const float4*)w_qkv, (const float4*)w_o);

    // 2) QKV projection -> per-head fp16 planes (Q pre-scaled 1/8)
    gemm_f16_kernel<<<dim3(24, 64), 256, GSMEM>>>(xp, wq, nullptr, 3 * DMODEL, 1);
    // 3) causal flash attention -> heads fp16
    attn_f16_kernel<<<dim3(SEQ / 128, BH), 256, A_TOTAL>>>();
    // 4) output projection
    gemm_f16_kernel<<<dim3(8, 64), 256, GSMEM>>>(hs, wo, out, DMODEL, 0);
}

// round 15
// speedup vs baseline: 1.5335x; 1.5335x over previous
#include <cuda_runtime.h>
#include <cuda_fp16.h>
#include <stdint.h>

// Problem constants
#define BATCH   4
#define HEADS   16
#define SEQ     2048
#define DK      64
#define DMODEL  1024
#define NTOK    (BATCH * SEQ)            // 8192
#define BH      (BATCH * HEADS)          // 64

// Scratch (device globals: cudaMalloc is forbidden)
__device__ __half g_x  [NTOK * DMODEL];          // x fp16
__device__ __half g_wq [3 * DMODEL * DMODEL];
__device__ __half g_wo [DMODEL * DMODEL];
__device__ __half g_q  [BH * SEQ * DK];          // Q fp16 (pre-scaled 1/8)
__device__ __half g_ks [BH * SEQ * DK];          // K fp16
__device__ __half g_vs [BH * SEQ * DK];          // V fp16
__device__ __half g_hs [NTOK * DMODEL];          // heads fp16

// ---------------------------------------------------------------------------
// Warp MMA + async-copy helpers (sm_80+ instructions only)
// ---------------------------------------------------------------------------
__device__ __forceinline__ uint32_t smem_u32(const void* p) {
    uint32_t a;
    asm("{ .reg .u64 t; cvta.to.shared.u64 t, %1; cvt.u32.u64 %0, t; }"
        : "=r"(a) : "l"(p));
    return a;
}
__device__ __forceinline__ void ldsm_x4(uint32_t& r0, uint32_t& r1,
                                        uint32_t& r2, uint32_t& r3, uint32_t addr) {
    asm volatile("ldmatrix.sync.aligned.m8n8.x4.shared.b16 {%0,%1,%2,%3}, [%4];"
                 : "=r"(r0), "=r"(r1), "=r"(r2), "=r"(r3) : "r"(addr));
}
__device__ __forceinline__ void ldsm_x4t(uint32_t& r0, uint32_t& r1,
                                         uint32_t& r2, uint32_t& r3, uint32_t addr) {
    asm volatile("ldmatrix.sync.aligned.m8n8.x4.trans.shared.b16 {%0,%1,%2,%3}, [%4];"
                 : "=r"(r0), "=r"(r1), "=r"(r2), "=r"(r3) : "r"(addr));
}
__device__ __forceinline__ void mma_f16(float* c, const uint32_t* a, const uint32_t* b) {
    asm volatile("mma.sync.aligned.m16n8k16.row.col.f32.f16.f16.f32 "
                 "{%0,%1,%2,%3}, {%4,%5,%6,%7}, {%8,%9}, {%0,%1,%2,%3};"
                 : "+f"(c[0]), "+f"(c[1]), "+f"(c[2]), "+f"(c[3])
                 : "r"(a[0]), "r"(a[1]), "r"(a[2]), "r"(a[3]),
                   "r"(b[0]), "r"(b[1]));
}
__device__ __forceinline__ uint32_t pack_f16(float a, float b) {
    __half2 h = __floats2half2_rn(a, b);
    return *(uint32_t*)&h;
}
__device__ __forceinline__ void cp16(uint32_t s, const void* g) {
    asm volatile("cp.async.cg.shared.global [%0], [%1], 16;" :: "r"(s), "l"(g));
}
#define CP_COMMIT() asm volatile("cp.async.commit_group;")
#define CP_WAIT1()  asm volatile("cp.async.wait_group 1;")

// ---------------------------------------------------------------------------
// Single fused fp32 -> fp16 convert for x, W_qkv, W_o  (one launch)
// ---------------------------------------------------------------------------
#define XN4   (NTOK * DMODEL / 4)                // 2097152
#define WQN4  (3 * DMODEL * DMODEL / 4)          // 786432
#define WON4  (DMODEL * DMODEL / 4)              // 262144
#define CVTN4 (XN4 + WQN4 + WON4)                // 3145728

__global__ __launch_bounds__(256)
void convert_all_kernel(const float4* __restrict__ x,
                        const float4* __restrict__ wq,
                        const float4* __restrict__ wo)
{
    int i = blockIdx.x * blockDim.x + threadIdx.x;
    if (i >= CVTN4) return;
    const float4* src;
    __half* dst;
    int j = i;
    if (j < XN4)                { src = x;  dst = g_x;  }
    else if ((j -= XN4) < WQN4) { src = wq; dst = g_wq; }
    else                        { j -= WQN4; src = wo; dst = g_wo; }
    float4 v = src[j];
    *(__half2*)(dst + 4 * (size_t)j)     = __floats2half2_rn(v.x, v.y);
    *(__half2*)(dst + 4 * (size_t)j + 2) = __floats2half2_rn(v.z, v.w);
}

// ---------------------------------------------------------------------------
// fp16 GEMM on HMMA (exact R11 config — best measured):
// C[M,N] = A[M,K] * B[N,K]^T, K = 1024.
// 256 threads = 8 warps (2m x 4n), warp tile 64x32, BK=64.
// 3-stage cp.async ring, one barrier per k-chunk (16 chunks).
// Inner loop: ALL ldsm front-batched (MLP), then 16-MMA chain.
// mode 0: fp32 store to C.  mode 1: QKV epilogue -> per-head fp16 planes.
// ---------------------------------------------------------------------------
#define BKS      64
#define NKI      (DMODEL / BKS)         // 16
#define GROW     144                    // 128B data + 16B pad per row
#define APLANE   (128 * GROW)           // 18432 bytes
#define STAGE_B2 (2 * APLANE)           // A, B
#define NSTG     3
#define GSMEM    (NSTG * STAGE_B2)      // 110592 bytes

__global__ __launch_bounds__(256, 1)
void gemm_f16_kernel(const __half* __restrict__ A,
                     const __half* __restrict__ B,
                     float* __restrict__ C, int N, int mode)
{
    extern __shared__ char smem[];
    const uint32_t sbase = smem_u32(smem);
    const int tid  = threadIdx.x;
    const int wid  = tid >> 5;
    const int lane = tid & 31;
    const int wm   = wid >> 2;          // 0..1  (64-row slab)
    const int wn   = wid & 3;           // 0..3  (32-col slab)
    const int m0   = blockIdx.y * 128;
    const int n0   = blockIdx.x * 128;
    const int K    = DMODEL;

    const __half* gA = A + (size_t)m0 * K;
    const __half* gB = B + (size_t)n0 * K;

    const int r2 = tid >> 1;            // 0..127
    const int c4 = (tid & 1) * 4;       // 16B-chunk base (0 or 4)
    auto issue_stage = [&](int buf, int kc) {
        const uint32_t dst = sbase + buf * STAGE_B2 + r2 * GROW;
        const size_t goff = (size_t)r2 * K + kc;
#pragma unroll
        for (int j = 0; j < 4; ++j) {
            cp16(dst + (c4 + j) * 16,          gA + goff + (c4 + j) * 8);
            cp16(dst + APLANE + (c4 + j) * 16, gB + goff + (c4 + j) * 8);
        }
    };

    issue_stage(0, 0);      CP_COMMIT();
    issue_stage(1, BKS);    CP_COMMIT();

    float acc[4][4][4];
#pragma unroll
    for (int mi = 0; mi < 4; ++mi)
#pragma unroll
        for (int nj = 0; nj < 4; ++nj)
#pragma unroll
            for (int q = 0; q < 4; ++q) acc[mi][nj][q] = 0.0f;

    for (int kt = 0; kt < NKI; ++kt) {
        CP_WAIT1();
        __syncthreads();
        if (kt + 2 < NKI) {
            issue_stage((kt + 2) % NSTG, (kt + 2) * BKS);
            CP_COMMIT();
        }

        const uint32_t sb = sbase + (kt % NSTG) * STAGE_B2;
#pragma unroll
        for (int ks = 0; ks < 4; ++ks) {
            uint32_t a_[4][4], b[4][2];
#pragma unroll
            for (int mi = 0; mi < 4; ++mi) {
                const int row = wm * 64 + mi * 16 + (lane & 15);
                const uint32_t a = sb + row * GROW + ks * 32 + (lane >> 4) * 16;
                ldsm_x4(a_[mi][0], a_[mi][1], a_[mi][2], a_[mi][3], a);
            }
#pragma unroll
            for (int p2 = 0; p2 < 2; ++p2) {
                const int row = wn * 32 + p2 * 16 + (lane & 15);
                const uint32_t a = sb + APLANE + row * GROW
                                 + ks * 32 + (lane >> 4) * 16;
                uint32_t r0, r1, r2x, r3;
                ldsm_x4(r0, r1, r2x, r3, a);
                b[2 * p2][0] = r0; b[2 * p2][1] = r2x;
                b[2 * p2 + 1][0] = r1; b[2 * p2 + 1][1] = r3;
            }
#pragma unroll
            for (int mi = 0; mi < 4; ++mi)
#pragma unroll
                for (int nj = 0; nj < 4; ++nj)
                    mma_f16(acc[mi][nj], a_[mi], b[nj]);
        }
    }

#pragma unroll
    for (int mi = 0; mi < 4; ++mi)
#pragma unroll
        for (int nj = 0; nj < 4; ++nj) {
            const int mrow = m0 + wm * 64 + mi * 16 + (lane >> 2);
            const int ncol = n0 + wn * 32 + nj * 8 + (lane & 3) * 2;
            if (mode == 0) {
                *(float2*)(C + (size_t)mrow * N + ncol) =
                    make_float2(acc[mi][nj][0], acc[mi][nj][1]);
                *(float2*)(C + (size_t)(mrow + 8) * N + ncol) =
                    make_float2(acc[mi][nj][2], acc[mi][nj][3]);
            } else {
                const int cc = ncol >> 10;
                const int h  = (ncol >> 6) & (HEADS - 1);
                const int dk = ncol & (DK - 1);
                const float scl = (cc == 0) ? 0.125f : 1.0f;
                __half* dstp = (cc == 0) ? g_q : ((cc == 1) ? g_ks : g_vs);
#pragma unroll
                for (int half_ = 0; half_ < 2; ++half_) {
                    const int m = mrow + half_ * 8;
                    const int b_ = m >> 11;
                    const int s  = m & (SEQ - 1);
                    const size_t off =
                        ((size_t)(b_ * HEADS + h) * SEQ + s) * DK + dk;
                    *(__half2*)(dstp + off) = __floats2half2_rn(
                        acc[mi][nj][half_ * 2] * scl,
                        acc[mi][nj][half_ * 2 + 1] * scl);
                }
            }
        }
}

// ---------------------------------------------------------------------------
// Causal flash attention on HMMA, fp16 (exact R11 version — register prefetch).
// Grid: (SEQ/128, BH). Block: 256 threads = 8 warps; warp owns 16 q-rows.
// ---------------------------------------------------------------------------
#define ASTR   144                    // 64 fp16 = 128B data + 16 pad
#define A_Q    0
#define A_K    (128 * ASTR)
#define A_V    (A_K + 64 * ASTR)
#define A_TOTAL (A_V + 64 * ASTR)     // 36864 bytes

__global__ __launch_bounds__(256, 1)
void attn_f16_kernel()
{
    extern __shared__ char smem[];
    const uint32_t sb = smem_u32(smem);
    const int tid  = threadIdx.x;
    const int w    = tid >> 5;
    const int lane = tid & 31;
    const int qt   = blockIdx.x;          // 128-row q tile
    const int bh   = blockIdx.y;
    const int q0   = qt * 128;

    const __half* Qs = g_q  + ((size_t)bh * SEQ + q0) * DK;
    const __half* Ks = g_ks + (size_t)bh * SEQ * DK;
    const __half* Vs = g_vs + (size_t)bh * SEQ * DK;

    const int r_ = tid >> 3;              // 0..31
    const int c_ = tid & 7;               // 16B chunk

    // Load Q tile (128 x 64) + KV tile 0 into smem
#pragma unroll
    for (int t = 0; t < 4; ++t) {
        const int row = r_ + t * 32;
        *(uint4*)(smem + A_Q + row * ASTR + c_ * 16) =
            *(const uint4*)(Qs + (size_t)row * DK + c_ * 8);
    }
#pragma unroll
    for (int t = 0; t < 2; ++t) {
        const int row = r_ + t * 32;
        const size_t g = (size_t)row * DK + c_ * 8;
        const int so = row * ASTR + c_ * 16;
        *(uint4*)(smem + A_K + so) = *(const uint4*)(Ks + g);
        *(uint4*)(smem + A_V + so) = *(const uint4*)(Vs + g);
    }
    __syncthreads();

    // Q fragments (registers, whole kernel)
    uint32_t qf[4][4];
#pragma unroll
    for (int kk = 0; kk < 4; ++kk) {
        const int row = w * 16 + (lane & 15);
        const uint32_t a = sb + A_Q + row * ASTR + kk * 32 + (lane >> 4) * 16;
        ldsm_x4(qf[kk][0], qf[kk][1], qf[kk][2], qf[kk][3], a);
    }

    float o[8][4];
#pragma unroll
    for (int nj = 0; nj < 8; ++nj)
#pragma unroll
        for (int q = 0; q < 4; ++q) o[nj][q] = 0.0f;
    float mA = -1e30f, mB = -1e30f, lA = 0.0f, lB = 0.0f;

    const int nkt = 2 * qt + 2;
    for (int kt = 0; kt < nkt; ++kt) {
        // Prefetch next KV tile into registers
        uint4 pf[4];
        const bool havepf = (kt + 1 < nkt);
        if (havepf) {
#pragma unroll
            for (int t = 0; t < 2; ++t) {
                const int row = r_ + t * 32;
                const size_t g = (size_t)((kt + 1) * 64 + row) * DK + c_ * 8;
                pf[t * 2 + 0] = *(const uint4*)(Ks + g);
                pf[t * 2 + 1] = *(const uint4*)(Vs + g);
            }
        }

        // Warps 0-3 fully masked on the last diagonal tile
        if (!(kt == 2 * qt + 1 && w < 4)) {
            // ---- S = Q K^T ----
            float s[8][4];
#pragma unroll
            for (int nj = 0; nj < 8; ++nj)
#pragma unroll
                for (int q = 0; q < 4; ++q) s[nj][q] = 0.0f;

#pragma unroll
            for (int kk = 0; kk < 4; ++kk) {
                uint32_t bk[8][2];
#pragma unroll
                for (int p2 = 0; p2 < 4; ++p2) {
                    const uint32_t a = sb + A_K + (p2 * 16 + (lane & 15)) * ASTR
                                     + kk * 32 + (lane >> 4) * 16;
                    uint32_t r0, r1, r2, r3;
                    ldsm_x4(r0, r1, r2, r3, a);
                    bk[2 * p2][0] = r0; bk[2 * p2][1] = r2;
                    bk[2 * p2 + 1][0] = r1; bk[2 * p2 + 1][1] = r3;
                }
#pragma unroll
                for (int nj = 0; nj < 8; ++nj)
                    mma_f16(s[nj], qf[kk], bk[nj]);
            }

            // ---- causal mask (diagonal tiles only) ----
            if (kt >= 2 * qt) {
                const int rowA = q0 + w * 16 + (lane >> 2);
                const int k0   = kt * 64;
#pragma unroll
                for (int nj = 0; nj < 8; ++nj) {
                    const int c0 = k0 + nj * 8 + (lane & 3) * 2;
                    if (c0 > rowA)     s[nj][0] = -1e30f;
                    if (c0 + 1 > rowA) s[nj][1] = -1e30f;
                    if (c0 > rowA + 8)     s[nj][2] = -1e30f;
                    if (c0 + 1 > rowA + 8) s[nj][3] = -1e30f;
                }
            }

            // ---- online softmax ----
            float tmA = -1e30f, tmB = -1e30f;
#pragma unroll
            for (int nj = 0; nj < 8; ++nj) {
                tmA = fmaxf(tmA, fmaxf(s[nj][0], s[nj][1]));
                tmB = fmaxf(tmB, fmaxf(s[nj][2], s[nj][3]));
            }
            tmA = fmaxf(tmA, __shfl_xor_sync(0xffffffffu, tmA, 1));
            tmA = fmaxf(tmA, __shfl_xor_sync(0xffffffffu, tmA, 2));
            tmB = fmaxf(tmB, __shfl_xor_sync(0xffffffffu, tmB, 1));
            tmB = fmaxf(tmB, __shfl_xor_sync(0xffffffffu, tmB, 2));
            const float mnA = fmaxf(mA, tmA);
            const float mnB = fmaxf(mB, tmB);
            const float fA = __expf(mA - mnA);
            const float fB = __expf(mB - mnB);
            mA = mnA; mB = mnB;

            float rsA = 0.0f, rsB = 0.0f;
#pragma unroll
            for (int nj = 0; nj < 8; ++nj) {
                s[nj][0] = __expf(s[nj][0] - mnA);
                s[nj][1] = __expf(s[nj][1] - mnA);
                s[nj][2] = __expf(s[nj][2] - mnB);
                s[nj][3] = __expf(s[nj][3] - mnB);
                rsA += s[nj][0] + s[nj][1];
                rsB += s[nj][2] + s[nj][3];
            }
            rsA += __shfl_xor_sync(0xffffffffu, rsA, 1);
            rsA += __shfl_xor_sync(0xffffffffu, rsA, 2);
            rsB += __shfl_xor_sync(0xffffffffu, rsB, 1);
            rsB += __shfl_xor_sync(0xffffffffu, rsB, 2);
            lA = lA * fA + rsA;
            lB = lB * fB + rsB;
#pragma unroll
            for (int nj = 0; nj < 8; ++nj) {
                o[nj][0] *= fA; o[nj][1] *= fA;
                o[nj][2] *= fB; o[nj][3] *= fB;
            }

            // ---- O += P V (P rounded to fp16) ----
#pragma unroll
            for (int kk = 0; kk < 4; ++kk) {
                const int j0 = 2 * kk, j1 = 2 * kk + 1;
                uint32_t ph[4];
                ph[0] = pack_f16(s[j0][0], s[j0][1]);
                ph[1] = pack_f16(s[j0][2], s[j0][3]);
                ph[2] = pack_f16(s[j1][0], s[j1][1]);
                ph[3] = pack_f16(s[j1][2], s[j1][3]);
#pragma unroll
                for (int p2 = 0; p2 < 4; ++p2) {
                    const uint32_t a = sb + A_V
                        + (kk * 16 + (lane & 7) + ((lane >> 3) & 1) * 8) * ASTR
                        + p2 * 32 + (lane >> 4) * 16;
                    uint32_t r0, r1, r2, r3;
                    ldsm_x4t(r0, r1, r2, r3, a);
                    uint32_t bv0[2] = {r0, r1}, bv1[2] = {r2, r3};
                    mma_f16(o[2 * p2],     ph, bv0);
                    mma_f16(o[2 * p2 + 1], ph, bv1);
                }
            }
        }

        if (havepf) {
            __syncthreads();
#pragma unroll
            for (int t = 0; t < 2; ++t) {
                const int row = r_ + t * 32;
                const int so = row * ASTR + c_ * 16;
                *(uint4*)(smem + A_K + so) = pf[t * 2 + 0];
                *(uint4*)(smem + A_V + so) = pf[t * 2 + 1];
            }
            __syncthreads();
        }
    }

    // ---- normalize + store heads [b*S+s][h*DK+dk] as fp16 ----
    const int b = bh >> 4;
    const int h = bh & 15;
    const float iA = 1.0f / lA;
    const float iB = 1.0f / lB;
    const int rowA = q0 + w * 16 + (lane >> 2);
#pragma unroll
    for (int nj = 0; nj < 8; ++nj) {
        const int col = h * DK + nj * 8 + (lane & 3) * 2;
        size_t off = (size_t)(b * SEQ + rowA) * DMODEL + col;
        *(__half2*)(g_hs + off) =
            __floats2half2_rn(o[nj][0] * iA, o[nj][1] * iA);
        *(__half2*)(g_hs + off + 8 * DMODEL) =
            __floats2half2_rn(o[nj][2] * iB, o[nj][3] * iB);
    }
}

// ---------------------------------------------------------------------------
extern "C" void kernel_launch(void* const* d_in, const int* in_sizes, int n_in,
                              void* d_out, int out_size)
{
    const float* x     = (const float*)d_in[0];
    const float* w_qkv = (const float*)d_in[1];
    const float* w_o   = (const float*)d_in[2];
    float* out = (float*)d_out;

    __half *xp, *wq, *wo, *hs;
    cudaGetSymbolAddress((void**)&xp, g_x);
    cudaGetSymbolAddress((void**)&wq, g_wq);
    cudaGetSymbolAddress((void**)&wo, g_wo);
    cudaGetSymbolAddress((void**)&hs, g_hs);

    cudaFuncSetAttribute(gemm_f16_kernel,
                         cudaFuncAttributeMaxDynamicSharedMemorySize, GSMEM);
    cudaFuncSetAttribute(attn_f16_kernel,
                         cudaFuncAttributeMaxDynamicSharedMemorySize, A_TOTAL);

    // 1) convert all inputs to fp16 (one launch)
    convert_all_kernel<<<(CVTN4 + 255) / 256, 256>>>(
        (const float4*)x, (const float4*)w_qkv, (const float4*)w_o);

    // 2) QKV projection -> per-head fp16 planes (Q pre-scaled 1/8)
    gemm_f16_kernel<<<dim3(24, 64), 256, GSMEM>>>(xp, wq, nullptr, 3 * DMODEL, 1);
    // 3) causal flash attention -> heads fp16
    attn_f16_kernel<<<dim3(SEQ / 128, BH), 256, A_TOTAL>>>();
    // 4) output projection
    gemm_f16_kernel<<<dim3(8, 64), 256, GSMEM>>>(hs, wo, out, DMODEL, 0);
}

// round 16
// speedup vs baseline: 1.5401x; 1.0043x over previous
#include <cuda_runtime.h>
#include <cuda_fp16.h>
#include <stdint.h>

// Problem constants
#define BATCH   4
#define HEADS   16
#define SEQ     2048
#define DK      64
#define DMODEL  1024
#define NTOK    (BATCH * SEQ)            // 8192
#define BH      (BATCH * HEADS)          // 64

// Scratch (device globals: cudaMalloc is forbidden)
__device__ __half g_x  [NTOK * DMODEL];          // x fp16
__device__ __half g_wq [3 * DMODEL * DMODEL];
__device__ __half g_wo [DMODEL * DMODEL];
__device__ __half g_q  [BH * SEQ * DK];          // Q fp16 (pre-scaled log2e/8)
__device__ __half g_ks [BH * SEQ * DK];          // K fp16
__device__ __half g_vs [BH * SEQ * DK];          // V fp16
__device__ __half g_hs [NTOK * DMODEL];          // heads fp16

// ---------------------------------------------------------------------------
// Warp MMA + async-copy helpers (sm_80+ instructions only)
// ---------------------------------------------------------------------------
__device__ __forceinline__ uint32_t smem_u32(const void* p) {
    uint32_t a;
    asm("{ .reg .u64 t; cvta.to.shared.u64 t, %1; cvt.u32.u64 %0, t; }"
        : "=r"(a) : "l"(p));
    return a;
}
__device__ __forceinline__ void ldsm_x4(uint32_t& r0, uint32_t& r1,
                                        uint32_t& r2, uint32_t& r3, uint32_t addr) {
    asm volatile("ldmatrix.sync.aligned.m8n8.x4.shared.b16 {%0,%1,%2,%3}, [%4];"
                 : "=r"(r0), "=r"(r1), "=r"(r2), "=r"(r3) : "r"(addr));
}
__device__ __forceinline__ void ldsm_x4t(uint32_t& r0, uint32_t& r1,
                                         uint32_t& r2, uint32_t& r3, uint32_t addr) {
    asm volatile("ldmatrix.sync.aligned.m8n8.x4.trans.shared.b16 {%0,%1,%2,%3}, [%4];"
                 : "=r"(r0), "=r"(r1), "=r"(r2), "=r"(r3) : "r"(addr));
}
__device__ __forceinline__ void mma_f16(float* c, const uint32_t* a, const uint32_t* b) {
    asm volatile("mma.sync.aligned.m16n8k16.row.col.f32.f16.f16.f32 "
                 "{%0,%1,%2,%3}, {%4,%5,%6,%7}, {%8,%9}, {%0,%1,%2,%3};"
                 : "+f"(c[0]), "+f"(c[1]), "+f"(c[2]), "+f"(c[3])
                 : "r"(a[0]), "r"(a[1]), "r"(a[2]), "r"(a[3]),
                   "r"(b[0]), "r"(b[1]));
}
__device__ __forceinline__ uint32_t pack_f16(float a, float b) {
    __half2 h = __floats2half2_rn(a, b);
    return *(uint32_t*)&h;
}
__device__ __forceinline__ float ex2(float x) {
    float y;
    asm("ex2.approx.f32 %0, %1;" : "=f"(y) : "f"(x));
    return y;
}
__device__ __forceinline__ void cp16(uint32_t s, const void* g) {
    asm volatile("cp.async.cg.shared.global [%0], [%1], 16;" :: "r"(s), "l"(g));
}
#define CP_COMMIT() asm volatile("cp.async.commit_group;")
#define CP_WAIT1()  asm volatile("cp.async.wait_group 1;")

// Q pre-scale: (1/sqrt(DK)) * log2(e)
#define QSCALE 0.1803368801111204f

// ---------------------------------------------------------------------------
// Single fused fp32 -> fp16 convert for x, W_qkv, W_o  (one launch)
// ---------------------------------------------------------------------------
#define XN4   (NTOK * DMODEL / 4)                // 2097152
#define WQN4  (3 * DMODEL * DMODEL / 4)          // 786432
#define WON4  (DMODEL * DMODEL / 4)              // 262144
#define CVTN4 (XN4 + WQN4 + WON4)                // 3145728

__global__ __launch_bounds__(256)
void convert_all_kernel(const float4* __restrict__ x,
                        const float4* __restrict__ wq,
                        const float4* __restrict__ wo)
{
    int i = blockIdx.x * blockDim.x + threadIdx.x;
    if (i >= CVTN4) return;
    const float4* src;
    __half* dst;
    int j = i;
    if (j < XN4)                { src = x;  dst = g_x;  }
    else if ((j -= XN4) < WQN4) { src = wq; dst = g_wq; }
    else                        { j -= WQN4; src = wo; dst = g_wo; }
    float4 v = src[j];
    *(__half2*)(dst + 4 * (size_t)j)     = __floats2half2_rn(v.x, v.y);
    *(__half2*)(dst + 4 * (size_t)j + 2) = __floats2half2_rn(v.z, v.w);
}

// ---------------------------------------------------------------------------
// fp16 GEMM on HMMA (R11 config — best measured):
// C[M,N] = A[M,K] * B[N,K]^T, K = 1024.
// 256 threads = 8 warps (2m x 4n), warp tile 64x32, BK=64.
// 3-stage cp.async ring, one barrier per k-chunk (16 chunks).
// Inner loop: ALL ldsm front-batched (MLP), then 16-MMA chain.
// mode 0: fp32 store to C.  mode 1: QKV epilogue -> per-head fp16 planes.
// ---------------------------------------------------------------------------
#define BKS      64
#define NKI      (DMODEL / BKS)         // 16
#define GROW     144                    // 128B data + 16B pad per row
#define APLANE   (128 * GROW)           // 18432 bytes
#define STAGE_B2 (2 * APLANE)           // A, B
#define NSTG     3
#define GSMEM    (NSTG * STAGE_B2)      // 110592 bytes

__global__ __launch_bounds__(256, 1)
void gemm_f16_kernel(const __half* __restrict__ A,
                     const __half* __restrict__ B,
                     float* __restrict__ C, int N, int mode)
{
    extern __shared__ char smem[];
    const uint32_t sbase = smem_u32(smem);
    const int tid  = threadIdx.x;
    const int wid  = tid >> 5;
    const int lane = tid & 31;
    const int wm   = wid >> 2;          // 0..1  (64-row slab)
    const int wn   = wid & 3;           // 0..3  (32-col slab)
    const int m0   = blockIdx.y * 128;
    const int n0   = blockIdx.x * 128;
    const int K    = DMODEL;

    const __half* gA = A + (size_t)m0 * K;
    const __half* gB = B + (size_t)n0 * K;

    const int r2 = tid >> 1;            // 0..127
    const int c4 = (tid & 1) * 4;       // 16B-chunk base (0 or 4)
    auto issue_stage = [&](int buf, int kc) {
        const uint32_t dst = sbase + buf * STAGE_B2 + r2 * GROW;
        const size_t goff = (size_t)r2 * K + kc;
#pragma unroll
        for (int j = 0; j < 4; ++j) {
            cp16(dst + (c4 + j) * 16,          gA + goff + (c4 + j) * 8);
            cp16(dst + APLANE + (c4 + j) * 16, gB + goff + (c4 + j) * 8);
        }
    };

    issue_stage(0, 0);      CP_COMMIT();
    issue_stage(1, BKS);    CP_COMMIT();

    float acc[4][4][4];
#pragma unroll
    for (int mi = 0; mi < 4; ++mi)
#pragma unroll
        for (int nj = 0; nj < 4; ++nj)
#pragma unroll
            for (int q = 0; q < 4; ++q) acc[mi][nj][q] = 0.0f;

    for (int kt = 0; kt < NKI; ++kt) {
        CP_WAIT1();
        __syncthreads();
        if (kt + 2 < NKI) {
            issue_stage((kt + 2) % NSTG, (kt + 2) * BKS);
            CP_COMMIT();
        }

        const uint32_t sb = sbase + (kt % NSTG) * STAGE_B2;
#pragma unroll
        for (int ks = 0; ks < 4; ++ks) {
            uint32_t a_[4][4], b[4][2];
#pragma unroll
            for (int mi = 0; mi < 4; ++mi) {
                const int row = wm * 64 + mi * 16 + (lane & 15);
                const uint32_t a = sb + row * GROW + ks * 32 + (lane >> 4) * 16;
                ldsm_x4(a_[mi][0], a_[mi][1], a_[mi][2], a_[mi][3], a);
            }
#pragma unroll
            for (int p2 = 0; p2 < 2; ++p2) {
                const int row = wn * 32 + p2 * 16 + (lane & 15);
                const uint32_t a = sb + APLANE + row * GROW
                                 + ks * 32 + (lane >> 4) * 16;
                uint32_t r0, r1, r2x, r3;
                ldsm_x4(r0, r1, r2x, r3, a);
                b[2 * p2][0] = r0; b[2 * p2][1] = r2x;
                b[2 * p2 + 1][0] = r1; b[2 * p2 + 1][1] = r3;
            }
#pragma unroll
            for (int mi = 0; mi < 4; ++mi)
#pragma unroll
                for (int nj = 0; nj < 4; ++nj)
                    mma_f16(acc[mi][nj], a_[mi], b[nj]);
        }
    }

#pragma unroll
    for (int mi = 0; mi < 4; ++mi)
#pragma unroll
        for (int nj = 0; nj < 4; ++nj) {
            const int mrow = m0 + wm * 64 + mi * 16 + (lane >> 2);
            const int ncol = n0 + wn * 32 + nj * 8 + (lane & 3) * 2;
            if (mode == 0) {
                *(float2*)(C + (size_t)mrow * N + ncol) =
                    make_float2(acc[mi][nj][0], acc[mi][nj][1]);
                *(float2*)(C + (size_t)(mrow + 8) * N + ncol) =
                    make_float2(acc[mi][nj][2], acc[mi][nj][3]);
            } else {
                const int cc = ncol >> 10;
                const int h  = (ncol >> 6) & (HEADS - 1);
                const int dk = ncol & (DK - 1);
                const float scl = (cc == 0) ? QSCALE : 1.0f;
                __half* dstp = (cc == 0) ? g_q : ((cc == 1) ? g_ks : g_vs);
#pragma unroll
                for (int half_ = 0; half_ < 2; ++half_) {
                    const int m = mrow + half_ * 8;
                    const int b_ = m >> 11;
                    const int s  = m & (SEQ - 1);
                    const size_t off =
                        ((size_t)(b_ * HEADS + h) * SEQ + s) * DK + dk;
                    *(__half2*)(dstp + off) = __floats2half2_rn(
                        acc[mi][nj][half_ * 2] * scl,
                        acc[mi][nj][half_ * 2 + 1] * scl);
                }
            }
        }
}

// ---------------------------------------------------------------------------
// Causal flash attention on HMMA, fp16 (R11 body; softmax in base-2 domain).
// Grid: (SEQ/128, BH). Block: 256 threads = 8 warps; warp owns 16 q-rows.
// qt mapped longest-first so stragglers at the end are the cheap tiles.
// ---------------------------------------------------------------------------
#define ASTR   144                    // 64 fp16 = 128B data + 16 pad
#define A_Q    0
#define A_K    (128 * ASTR)
#define A_V    (A_K + 64 * ASTR)
#define A_TOTAL (A_V + 64 * ASTR)     // 36864 bytes

__global__ __launch_bounds__(256, 1)
void attn_f16_kernel()
{
    extern __shared__ char smem[];
    const uint32_t sb = smem_u32(smem);
    const int tid  = threadIdx.x;
    const int w    = tid >> 5;
    const int lane = tid & 31;
    const int qt   = (SEQ / 128 - 1) - blockIdx.x;   // longest-first
    const int bh   = blockIdx.y;
    const int q0   = qt * 128;

    const __half* Qs = g_q  + ((size_t)bh * SEQ + q0) * DK;
    const __half* Ks = g_ks + (size_t)bh * SEQ * DK;
    const __half* Vs = g_vs + (size_t)bh * SEQ * DK;

    const int r_ = tid >> 3;              // 0..31
    const int c_ = tid & 7;               // 16B chunk

    // Load Q tile (128 x 64) + KV tile 0 into smem
#pragma unroll
    for (int t = 0; t < 4; ++t) {
        const int row = r_ + t * 32;
        *(uint4*)(smem + A_Q + row * ASTR + c_ * 16) =
            *(const uint4*)(Qs + (size_t)row * DK + c_ * 8);
    }
#pragma unroll
    for (int t = 0; t < 2; ++t) {
        const int row = r_ + t * 32;
        const size_t g = (size_t)row * DK + c_ * 8;
        const int so = row * ASTR + c_ * 16;
        *(uint4*)(smem + A_K + so) = *(const uint4*)(Ks + g);
        *(uint4*)(smem + A_V + so) = *(const uint4*)(Vs + g);
    }
    __syncthreads();

    // Q fragments (registers, whole kernel)
    uint32_t qf[4][4];
#pragma unroll
    for (int kk = 0; kk < 4; ++kk) {
        const int row = w * 16 + (lane & 15);
        const uint32_t a = sb + A_Q + row * ASTR + kk * 32 + (lane >> 4) * 16;
        ldsm_x4(qf[kk][0], qf[kk][1], qf[kk][2], qf[kk][3], a);
    }

    float o[8][4];
#pragma unroll
    for (int nj = 0; nj < 8; ++nj)
#pragma unroll
        for (int q = 0; q < 4; ++q) o[nj][q] = 0.0f;
    float mA = -1e30f, mB = -1e30f, lA = 0.0f, lB = 0.0f;

    const int nkt = 2 * qt + 2;
    for (int kt = 0; kt < nkt; ++kt) {
        // Prefetch next KV tile into registers
        uint4 pf[4];
        const bool havepf = (kt + 1 < nkt);
        if (havepf) {
#pragma unroll
            for (int t = 0; t < 2; ++t) {
                const int row = r_ + t * 32;
                const size_t g = (size_t)((kt + 1) * 64 + row) * DK + c_ * 8;
                pf[t * 2 + 0] = *(const uint4*)(Ks + g);
                pf[t * 2 + 1] = *(const uint4*)(Vs + g);
            }
        }

        // Warps 0-3 fully masked on the last diagonal tile
        if (!(kt == 2 * qt + 1 && w < 4)) {
            // ---- S = Q K^T  (values already in log2 domain via QSCALE) ----
            float s[8][4];
#pragma unroll
            for (int nj = 0; nj < 8; ++nj)
#pragma unroll
                for (int q = 0; q < 4; ++q) s[nj][q] = 0.0f;

#pragma unroll
            for (int kk = 0; kk < 4; ++kk) {
                uint32_t bk[8][2];
#pragma unroll
                for (int p2 = 0; p2 < 4; ++p2) {
                    const uint32_t a = sb + A_K + (p2 * 16 + (lane & 15)) * ASTR
                                     + kk * 32 + (lane >> 4) * 16;
                    uint32_t r0, r1, r2, r3;
                    ldsm_x4(r0, r1, r2, r3, a);
                    bk[2 * p2][0] = r0; bk[2 * p2][1] = r2;
                    bk[2 * p2 + 1][0] = r1; bk[2 * p2 + 1][1] = r3;
                }
#pragma unroll
                for (int nj = 0; nj < 8; ++nj)
                    mma_f16(s[nj], qf[kk], bk[nj]);
            }

            // ---- causal mask (diagonal tiles only) ----
            if (kt >= 2 * qt) {
                const int rowA = q0 + w * 16 + (lane >> 2);
                const int k0   = kt * 64;
#pragma unroll
                for (int nj = 0; nj < 8; ++nj) {
                    const int c0 = k0 + nj * 8 + (lane & 3) * 2;
                    if (c0 > rowA)     s[nj][0] = -1e30f;
                    if (c0 + 1 > rowA) s[nj][1] = -1e30f;
                    if (c0 > rowA + 8)     s[nj][2] = -1e30f;
                    if (c0 + 1 > rowA + 8) s[nj][3] = -1e30f;
                }
            }

            // ---- online softmax (base-2) ----
            float tmA = -1e30f, tmB = -1e30f;
#pragma unroll
            for (int nj = 0; nj < 8; ++nj) {
                tmA = fmaxf(tmA, fmaxf(s[nj][0], s[nj][1]));
                tmB = fmaxf(tmB, fmaxf(s[nj][2], s[nj][3]));
            }
            tmA = fmaxf(tmA, __shfl_xor_sync(0xffffffffu, tmA, 1));
            tmA = fmaxf(tmA, __shfl_xor_sync(0xffffffffu, tmA, 2));
            tmB = fmaxf(tmB, __shfl_xor_sync(0xffffffffu, tmB, 1));
            tmB = fmaxf(tmB, __shfl_xor_sync(0xffffffffu, tmB, 2));
            const float mnA = fmaxf(mA, tmA);
            const float mnB = fmaxf(mB, tmB);
            const float fA = ex2(mA - mnA);
            const float fB = ex2(mB - mnB);
            mA = mnA; mB = mnB;

            float rsA = 0.0f, rsB = 0.0f;
#pragma unroll
            for (int nj = 0; nj < 8; ++nj) {
                s[nj][0] = ex2(s[nj][0] - mnA);
                s[nj][1] = ex2(s[nj][1] - mnA);
                s[nj][2] = ex2(s[nj][2] - mnB);
                s[nj][3] = ex2(s[nj][3] - mnB);
                rsA += s[nj][0] + s[nj][1];
                rsB += s[nj][2] + s[nj][3];
            }
            rsA += __shfl_xor_sync(0xffffffffu, rsA, 1);
            rsA += __shfl_xor_sync(0xffffffffu, rsA, 2);
            rsB += __shfl_xor_sync(0xffffffffu, rsB, 1);
            rsB += __shfl_xor_sync(0xffffffffu, rsB, 2);
            lA = lA * fA + rsA;
            lB = lB * fB + rsB;
#pragma unroll
            for (int nj = 0; nj < 8; ++nj) {
                o[nj][0] *= fA; o[nj][1] *= fA;
                o[nj][2] *= fB; o[nj][3] *= fB;
            }

            // ---- O += P V (P rounded to fp16) ----
#pragma unroll
            for (int kk = 0; kk < 4; ++kk) {
                const int j0 = 2 * kk, j1 = 2 * kk + 1;
                uint32_t ph[4];
                ph[0] = pack_f16(s[j0][0], s[j0][1]);
                ph[1] = pack_f16(s[j0][2], s[j0][3]);
                ph[2] = pack_f16(s[j1][0], s[j1][1]);
                ph[3] = pack_f16(s[j1][2], s[j1][3]);
#pragma unroll
                for (int p2 = 0; p2 < 4; ++p2) {
                    const uint32_t a = sb + A_V
                        + (kk * 16 + (lane & 7) + ((lane >> 3) & 1) * 8) * ASTR
                        + p2 * 32 + (lane >> 4) * 16;
                    uint32_t r0, r1, r2, r3;
                    ldsm_x4t(r0, r1, r2, r3, a);
                    uint32_t bv0[2] = {r0, r1}, bv1[2] = {r2, r3};
                    mma_f16(o[2 * p2],     ph, bv0);
                    mma_f16(o[2 * p2 + 1], ph, bv1);
                }
            }
        }

        if (havepf) {
            __syncthreads();
#pragma unroll
            for (int t = 0; t < 2; ++t) {
                const int row = r_ + t * 32;
                const int so = row * ASTR + c_ * 16;
                *(uint4*)(smem + A_K + so) = pf[t * 2 + 0];
                *(uint4*)(smem + A_V + so) = pf[t * 2 + 1];
            }
            __syncthreads();
        }
    }

    // ---- normalize + store heads [b*S+s][h*DK+dk] as fp16 ----
    const int b = bh >> 4;
    const int h = bh & 15;
    const float iA = 1.0f / lA;
    const float iB = 1.0f / lB;
    const int rowA = q0 + w * 16 + (lane >> 2);
#pragma unroll
    for (int nj = 0; nj < 8; ++nj) {
        const int col = h * DK + nj * 8 + (lane & 3) * 2;
        size_t off = (size_t)(b * SEQ + rowA) * DMODEL + col;
        *(__half2*)(g_hs + off) =
            __floats2half2_rn(o[nj][0] * iA, o[nj][1] * iA);
        *(__half2*)(g_hs + off + 8 * DMODEL) =
            __floats2half2_rn(o[nj][2] * iB, o[nj][3] * iB);
    }
}

// ---------------------------------------------------------------------------
extern "C" void kernel_launch(void* const* d_in, const int* in_sizes, int n_in,
                              void* d_out, int out_size)
{
    const float* x     = (const float*)d_in[0];
    const float* w_qkv = (const float*)d_in[1];
    const float* w_o   = (const float*)d_in[2];
    float* out = (float*)d_out;

    __half *xp, *wq, *wo, *hs;
    cudaGetSymbolAddress((void**)&xp, g_x);
    cudaGetSymbolAddress((void**)&wq, g_wq);
    cudaGetSymbolAddress((void**)&wo, g_wo);
    cudaGetSymbolAddress((void**)&hs, g_hs);

    cudaFuncSetAttribute(gemm_f16_kernel,
                         cudaFuncAttributeMaxDynamicSharedMemorySize, GSMEM);
    cudaFuncSetAttribute(attn_f16_kernel,
                         cudaFuncAttributeMaxDynamicSharedMemorySize, A_TOTAL);

    // 1) convert all inputs to fp16 (one launch)
    convert_all_kernel<<<(CVTN4 + 255) / 256, 256>>>(
        (const float4*)x, (const float4*)w_qkv, (const float4*)w_o);

    // 2) QKV projection -> per-head fp16 planes (Q pre-scaled log2e/8)
    gemm_f16_kernel<<<dim3(24, 64), 256, GSMEM>>>(xp, wq, nullptr, 3 * DMODEL, 1);
    // 3) causal flash attention -> heads fp16
    attn_f16_kernel<<<dim3(SEQ / 128, BH), 256, A_TOTAL>>>();
    // 4) output projection
    gemm_f16_kernel<<<dim3(8, 64), 256, GSMEM>>>(hs, wo, out, DMODEL, 0);
}